// round 8
// baseline (speedup 1.0000x reference)
#include <cuda_runtime.h>
#include <math.h>
#include <float.h>

// RMSPELoss R8: fully fused. Each 256-thread block owns 64 contiguous rows:
// filter-on-load int4 label scan -> rare-hit smem bitmap (spread ATOMS),
// logits prefetched in the same latency wave; one barrier; 64 threads do
// register-only 4x4 circular cost + 24-perm min; block reduce -> 1 RED.

#define BATCH 131072
#define NC 181
#define PI_F 3.14159265358979323846f
#define TWOPI_F 6.283185307179586f
#define INV_TWOPI_F 0.15915494309189535f

#define THREADS 256
#define ROWS 64
#define NBLOCKS (BATCH / ROWS)                       // 2048
#define INTS_PER_BLOCK (ROWS * NC)                   // 11584
#define INT4_PER_BLOCK (INTS_PER_BLOCK / 4)          // 2896
#define ITERS ((INT4_PER_BLOCK + THREADS - 1) / THREADS)   // 12
#define BITWORDS (ROWS * 6)                          // 6 x 32-bit words per row

__device__ double   g_acc;    // zero-init; reset by last block each call
__device__ unsigned g_done;   // zero-init; reset by last block each call

__global__ __launch_bounds__(THREADS)
void rmspe_fused(const float* __restrict__ logits, const int* __restrict__ labels,
                 float* __restrict__ out) {
    __shared__ unsigned s_bits[BITWORDS];
    __shared__ float    s_doa[ROWS * 4];
    __shared__ float    s_part[2];

    const int tid  = threadIdx.x;
    const int lane = tid & 31;
    const long row0 = (long)blockIdx.x * ROWS;

    // ---- init bitmap + prefetch this block's 256 logits scalars (same wave) ----
    if (tid < BITWORDS) s_bits[tid] = 0u;            // 384 > 256? no: BITWORDS=384
    if (tid + THREADS < BITWORDS) s_bits[tid + THREADS] = 0u;
    {
        int r = tid >> 2, k = tid & 3;               // 256 threads = 64 rows x 4
        s_doa[tid] = __ldg(&logits[(row0 + r) * NC + k]);
    }
    __syncthreads();

    // ---- phase 1: filter-on-load scan of the block's 46336B label region ----
    const int4* __restrict__ g4 =
        reinterpret_cast<const int4*>(labels + row0 * NC);
    #pragma unroll
    for (int it = 0; it < ITERS; it++) {
        int i = tid + it * THREADS;
        if (i < INT4_PER_BLOCK) {
            int4 v = __ldcs(&g4[i]);
            if ((v.x | v.y | v.z | v.w) != 0) {      // rare (~8.5% of int4s)
                int linear = i * 4;
                int vals[4] = {v.x, v.y, v.z, v.w};
                #pragma unroll
                for (int k = 0; k < 4; k++) {
                    if (vals[k] == 1) {
                        int l = linear + k;
                        int r = l / NC;              // local row 0..63 (mul-shift)
                        int c = l - r * NC;
                        atomicOr(&s_bits[r * 6 + (c >> 5)], 1u << (c & 31));
                    }
                }
            }
        }
    }
    __syncthreads();

    // ---- phase 2: threads 0..63 each finish one row, all in registers ----
    float rmse = 0.0f;
    if (tid < ROWS) {
        unsigned b0 = s_bits[tid * 6 + 0], b1 = s_bits[tid * 6 + 1];
        unsigned b2 = s_bits[tid * 6 + 2], b3 = s_bits[tid * 6 + 3];
        unsigned b4 = s_bits[tid * 6 + 4], b5 = s_bits[tid * 6 + 5];

        int idx[4];
        int n = 0;
        #define DRAIN(w, base) while (w) { int b = __ffs(w) - 1; w &= w - 1; idx[n++] = (base) + b; }
        DRAIN(b0, 0) DRAIN(b1, 32) DRAIN(b2, 64) DRAIN(b3, 96) DRAIN(b4, 128) DRAIN(b5, 160)
        #undef DRAIN

        float doa[4], ang[4];
        #pragma unroll
        for (int k = 0; k < 4; k++) {
            doa[k] = s_doa[tid * 4 + k];
            ang[k] = ((float)idx[k] - 90.0f) * (PI_F / 180.0f);
        }

        float cost[4][4];
        #pragma unroll
        for (int i = 0; i < 4; i++) {
            #pragma unroll
            for (int j = 0; j < 4; j++) {
                float x = doa[i] - ang[j] + PI_F;
                float m = x - TWOPI_F * floorf(x * INV_TWOPI_F);  // mod in [0,2pi)
                float d = m - PI_F;
                cost[i][j] = d * d;
            }
        }

        float best = FLT_MAX;
        #define P4(a,b,c,d) best = fminf(best, cost[0][a] + cost[1][b] + cost[2][c] + cost[3][d]);
        P4(0,1,2,3) P4(0,1,3,2) P4(0,2,1,3) P4(0,2,3,1) P4(0,3,1,2) P4(0,3,2,1)
        P4(1,0,2,3) P4(1,0,3,2) P4(1,2,0,3) P4(1,2,3,0) P4(1,3,0,2) P4(1,3,2,0)
        P4(2,0,1,3) P4(2,0,3,1) P4(2,1,0,3) P4(2,1,3,0) P4(2,3,0,1) P4(2,3,1,0)
        P4(3,0,1,2) P4(3,0,2,1) P4(3,1,0,2) P4(3,1,2,0) P4(3,2,0,1) P4(3,2,1,0)
        #undef P4

        rmse = sqrtf(best * 0.25f);
    }

    // ---- phase 3: reduce 64 values (warps 0 and 1) -> 1 double RED ----
    if (tid < ROWS) {
        #pragma unroll
        for (int off = 16; off; off >>= 1)
            rmse += __shfl_down_sync(0xffffffffu, rmse, off);
        if (lane == 0) s_part[tid >> 5] = rmse;
    }
    __syncthreads();

    if (tid == 0) {
        atomicAdd(&g_acc, (double)(s_part[0] + s_part[1]));
        __threadfence();
        unsigned prev = atomicAdd(&g_done, 1u);
        if (prev == NBLOCKS - 1) {
            __threadfence();
            double total = *((volatile double*)&g_acc);
            out[0] = (float)(total / (double)BATCH);
            g_acc  = 0.0;     // deterministic state for next graph replay
            g_done = 0u;
        }
    }
}

extern "C" void kernel_launch(void* const* d_in, const int* in_sizes, int n_in,
                              void* d_out, int out_size) {
    const float* logits = (const float*)d_in[0];
    const int*   labels = (const int*)d_in[1];
    float* out = (float*)d_out;

    rmspe_fused<<<NBLOCKS, THREADS>>>(logits, labels, out);
}

// round 9
// speedup vs baseline: 1.0780x; 1.0780x over previous
#include <cuda_runtime.h>
#include <math.h>
#include <float.h>

// RMSPELoss R9: two kernels (fusion regressed in R8). Scan = REDG bitmap at
// ~stream ceiling + NEW: compact logits pre-gather into g_doa (hides the
// 724B-stride scatter under the scan's spare issue/latency slots). Finish =
// 1 thread/row, fully coalesced L2-resident loads, register-only decode.

#define BATCH 131072
#define NC 181
#define PI_F 3.14159265358979323846f
#define TWOPI_F 6.283185307179586f
#define INV_TWOPI_F 0.15915494309189535f

#define TOTAL_INT4 (BATCH * NC / 4)                    // 5,931,008
#define SCAN_THREADS 256
#define SCAN_UNROLL 8
#define SCAN_BLOCKS (TOTAL_INT4 / (SCAN_THREADS * SCAN_UNROLL))   // 2896, exact
#define SCAN_STRIDE (SCAN_BLOCKS * SCAN_THREADS)                  // 741,376

#define FIN_THREADS 256
#define FIN_BLOCKS (BATCH / FIN_THREADS)               // 512

__device__ double   g_acc;    // zero-init; reset by epilogue each call
__device__ unsigned g_done;   // zero-init; reset by epilogue each call
// 3 x 64-bit words per row (192 bits >= 181). Zero-init; finish re-zeroes
// every word it reads, so each graph replay starts clean.
__device__ unsigned long long g_bits[BATCH * 3];
// compact copy of logits[:, 0:4], written by scan every call (same values)
__device__ __align__(16) float4 g_doa[BATCH];

// ---------------- kernel 1: streaming scan + logits pre-gather ----------------
__global__ __launch_bounds__(SCAN_THREADS)
void rmspe_scan(const float* __restrict__ logits, const int* __restrict__ labels) {
    const int t = blockIdx.x * SCAN_THREADS + threadIdx.x;
    const int4* __restrict__ g4 = reinterpret_cast<const int4*>(labels);

    // front-batched independent label loads: MLP = 8, perfectly coalesced
    int4 v[SCAN_UNROLL];
    #pragma unroll
    for (int j = 0; j < SCAN_UNROLL; j++)
        v[j] = __ldcs(&g4[t + j * SCAN_STRIDE]);

    // compact logits pre-gather: first BATCH threads copy row t's 4 scalars.
    // Scattered (724B-stride) reads hide under the label-stream latency.
    if (t < BATCH) {
        const float* lp = logits + (long)t * NC;
        float4 d;
        d.x = __ldg(lp);     d.y = __ldg(lp + 1);
        d.z = __ldg(lp + 2); d.w = __ldg(lp + 3);
        g_doa[t] = d;
    }

    #pragma unroll
    for (int j = 0; j < SCAN_UNROLL; j++) {
        int4 x = v[j];
        if ((x.x | x.y | x.z | x.w) != 0) {            // rare (~8.5% of int4s)
            int linear = (t + j * SCAN_STRIDE) * 4;
            int vals[4] = {x.x, x.y, x.z, x.w};
            #pragma unroll
            for (int k = 0; k < 4; k++) {
                if (vals[k] == 1) {
                    int l = linear + k;
                    int r = l / NC;                    // mul-shift by constant
                    int c = l - r * NC;
                    // result unused -> REDG (fire-and-forget, no return dep)
                    atomicOr(&g_bits[r * 3 + (c >> 6)], 1ull << (c & 63));
                }
            }
        }
    }
}

// pop the lowest set bit across a 192-bit value in 3 registers
__device__ __forceinline__ int pop_lowest(unsigned long long& w0,
                                          unsigned long long& w1,
                                          unsigned long long& w2) {
    if (w0) { int b = __ffsll((long long)w0) - 1; w0 &= w0 - 1; return b; }
    if (w1) { int b = __ffsll((long long)w1) - 1; w1 &= w1 - 1; return 64 + b; }
    {        int b = __ffsll((long long)w2) - 1; w2 &= w2 - 1; return 128 + b; }
}

// ---------------- kernel 2: one thread per row, all-coalesced ----------------
__global__ __launch_bounds__(FIN_THREADS)
void rmspe_finish(float* __restrict__ out) {
    __shared__ float s_warp[FIN_THREADS / 32];

    const int row  = blockIdx.x * FIN_THREADS + threadIdx.x;
    const int lane = threadIdx.x & 31;

    // ---- one latency wave: float4 doa + 3 bitmap words, all L2-resident ----
    float4 d = g_doa[row];
    unsigned long long* bp = &g_bits[row * 3];
    unsigned long long w0 = bp[0];
    unsigned long long w1 = bp[1];
    unsigned long long w2 = bp[2];

    // reset bitmap for the next graph replay (fire-and-forget stores)
    bp[0] = 0ull; bp[1] = 0ull; bp[2] = 0ull;

    // ---- extract the 4 one-positions into named registers ----
    int i0 = pop_lowest(w0, w1, w2);
    int i1 = pop_lowest(w0, w1, w2);
    int i2 = pop_lowest(w0, w1, w2);
    int i3 = pop_lowest(w0, w1, w2);

    float ang[4];
    ang[0] = ((float)i0 - 90.0f) * (PI_F / 180.0f);
    ang[1] = ((float)i1 - 90.0f) * (PI_F / 180.0f);
    ang[2] = ((float)i2 - 90.0f) * (PI_F / 180.0f);
    ang[3] = ((float)i3 - 90.0f) * (PI_F / 180.0f);
    float doa[4] = {d.x, d.y, d.z, d.w};

    float cost[4][4];
    #pragma unroll
    for (int i = 0; i < 4; i++) {
        #pragma unroll
        for (int j = 0; j < 4; j++) {
            float x = doa[i] - ang[j] + PI_F;
            float m = x - TWOPI_F * floorf(x * INV_TWOPI_F);  // mod in [0,2pi)
            float dd = m - PI_F;
            cost[i][j] = dd * dd;
        }
    }

    float best = FLT_MAX;
    #define P4(a,b,c,e) best = fminf(best, cost[0][a] + cost[1][b] + cost[2][c] + cost[3][e]);
    P4(0,1,2,3) P4(0,1,3,2) P4(0,2,1,3) P4(0,2,3,1) P4(0,3,1,2) P4(0,3,2,1)
    P4(1,0,2,3) P4(1,0,3,2) P4(1,2,0,3) P4(1,2,3,0) P4(1,3,0,2) P4(1,3,2,0)
    P4(2,0,1,3) P4(2,0,3,1) P4(2,1,0,3) P4(2,1,3,0) P4(2,3,0,1) P4(2,3,1,0)
    P4(3,0,1,2) P4(3,0,2,1) P4(3,1,0,2) P4(3,1,2,0) P4(3,2,0,1) P4(3,2,1,0)
    #undef P4

    float rmse = sqrtf(best * 0.25f);

    // ---- warp sum -> smem -> thread0 -> one double RED per block ----
    #pragma unroll
    for (int off = 16; off; off >>= 1)
        rmse += __shfl_down_sync(0xffffffffu, rmse, off);
    if (lane == 0) s_warp[threadIdx.x >> 5] = rmse;
    __syncthreads();

    if (threadIdx.x == 0) {
        float x = 0.0f;
        #pragma unroll
        for (int i = 0; i < FIN_THREADS / 32; i++) x += s_warp[i];
        atomicAdd(&g_acc, (double)x);
        __threadfence();
        unsigned prev = atomicAdd(&g_done, 1u);
        if (prev == FIN_BLOCKS - 1) {
            __threadfence();
            double total = *((volatile double*)&g_acc);
            out[0] = (float)(total / (double)BATCH);
            g_acc  = 0.0;     // deterministic state for next graph replay
            g_done = 0u;
        }
    }
}

extern "C" void kernel_launch(void* const* d_in, const int* in_sizes, int n_in,
                              void* d_out, int out_size) {
    const float* logits = (const float*)d_in[0];
    const int*   labels = (const int*)d_in[1];
    float* out = (float*)d_out;

    rmspe_scan<<<SCAN_BLOCKS, SCAN_THREADS>>>(logits, labels);
    rmspe_finish<<<FIN_BLOCKS, FIN_THREADS>>>(out);
}